// round 2
// baseline (speedup 1.0000x reference)
#include <cuda_runtime.h>

#define N_ 128
#define L_ 160
#define E_ 512
#define HE_ 512
#define HD_ 1024
#define T_ 128
#define LN_ (L_*N_)
#define G4E_ 2048
#define G4D_ 4096

// ---------------- scratch (device globals: no allocation allowed) ----------------
__device__ __align__(16) float g_xs[LN_*E_];                 // (l,n,e)  42 MB
__device__ __align__(16) float g_G[2][(size_t)LN_*G4E_];     // per-dir precomputed gates (reused enc0/enc1) 336 MB
__device__ __align__(16) float g_h1[(size_t)LN_*2*HE_];      // enc0 output concat  84 MB
__device__ __align__(16) float g_enc[(size_t)LN_*2*HE_];     // enc1 output concat  84 MB
__device__ __align__(16) float g_hst[2][2][N_*HE_];          // [phase][dir]
__device__ __align__(16) float g_cst[2][N_*HE_];             // [dir]
__device__ __align__(16) float g_dh[2][N_*HD_];              // decoder h ping-pong
__device__ __align__(16) float g_dc[N_*HD_];
__device__ int   g_amax[N_];
__device__ float g_lterm[L_*N_];

__device__ __forceinline__ float sigf(float x){ return 1.f/(1.f+expf(-x)); }

// ---------------- embedding lookup: xs[l][n][:] = embed[ids[n][l]] ----------------
__global__ void k_embed(const int* __restrict__ ids, const float* __restrict__ embed)
{
    int i = blockIdx.x*blockDim.x + threadIdx.x;   // one float4 per thread
    const int tot = LN_*E_/4;
    if (i >= tot) return;
    int e4 = i % (E_/4);
    int ln = i / (E_/4);
    int l = ln / N_, n = ln % N_;
    int id = ids[n*L_ + l];
    reinterpret_cast<float4*>(g_xs)[i] =
        reinterpret_cast<const float4*>(embed + (size_t)id*E_)[e4];
}

// ---------------- zero encoder states (both phases, both dirs, c) ----------------
__global__ void k_zero_enc()
{
    int i = blockIdx.x*blockDim.x + threadIdx.x;
    if (i < 2*2*N_*HE_) (&g_hst[0][0][0])[i] = 0.f;
    if (i < 2*N_*HE_)   (&g_cst[0][0])[i]    = 0.f;
}

// ---------------- big GEMM: C[z] = A(M x K) @ B[z](2048 x K)^T + bias[z] ----------------
// 128x128 block tile, 256 threads, 8x8 per thread, K-chunk 8
__global__ __launch_bounds__(256) void k_gemm_bias(int asel, const float* __restrict__ Ball,
                                                   const float* __restrict__ biasall, int K)
{
    const float* A = asel ? g_h1 : g_xs;
    int z = blockIdx.z;
    const float* B = Ball + (size_t)z * G4E_ * K;
    const float* bias = biasall + z * G4E_;
    float* C = g_G[z];
    int m0 = blockIdx.y * 128, n0 = blockIdx.x * 128;
    __shared__ __align__(16) float As[8][128];
    __shared__ __align__(16) float Bs[8][128];
    int tid = threadIdx.x;
    int lr = tid >> 1, lk = (tid & 1) * 4;
    int ry = (tid >> 4) * 8, cx = (tid & 15) * 8;
    float acc[8][8];
    #pragma unroll
    for (int i = 0; i < 8; i++)
        #pragma unroll
        for (int j = 0; j < 8; j++) acc[i][j] = 0.f;
    const float* Arow = A + (size_t)(m0+lr)*K + lk;
    const float* Brow = B + (size_t)(n0+lr)*K + lk;
    for (int kc = 0; kc < K; kc += 8) {
        float4 av = *(const float4*)(Arow + kc);
        float4 bv = *(const float4*)(Brow + kc);
        __syncthreads();
        As[lk+0][lr]=av.x; As[lk+1][lr]=av.y; As[lk+2][lr]=av.z; As[lk+3][lr]=av.w;
        Bs[lk+0][lr]=bv.x; Bs[lk+1][lr]=bv.y; Bs[lk+2][lr]=bv.z; Bs[lk+3][lr]=bv.w;
        __syncthreads();
        #pragma unroll
        for (int kk = 0; kk < 8; kk++) {
            float a[8], b[8];
            #pragma unroll
            for (int i = 0; i < 8; i++) a[i] = As[kk][ry+i];
            #pragma unroll
            for (int j = 0; j < 8; j++) b[j] = Bs[kk][cx+j];
            #pragma unroll
            for (int i = 0; i < 8; i++)
                #pragma unroll
                for (int j = 0; j < 8; j++)
                    acc[i][j] += a[i]*b[j];
        }
    }
    #pragma unroll
    for (int i = 0; i < 8; i++)
        #pragma unroll
        for (int j = 0; j < 8; j++)
            C[(size_t)(m0+ry+i)*G4E_ + n0+cx+j] = acc[i][j] + bias[n0+cx+j];
}

// ---------------- encoder LSTM step (both dirs in one launch) ----------------
// grid: (HE/16 unit-tiles, N/32, 2 dirs), 256 threads.
// Block computes a 32(n) x 64(col) tile where col = gate*16 + uu  -> wr = gate*HE + u0+uu.
__global__ __launch_bounds__(256) void k_lstm_enc(int layer, int t, int pin,
                                                  const float* __restrict__ whh_all)
{
    int d = blockIdx.z;
    int t_eff = d ? (L_-1-t) : t;
    int n0 = blockIdx.y * 32;
    int u0 = blockIdx.x * 16;
    const float* whh = whh_all + (size_t)d * G4E_ * HE_;
    const float* hin = g_hst[pin][d];
    __shared__ __align__(16) float As[16][32];
    __shared__ __align__(16) float Bs[16][64];
    int tid = threadIdx.x;
    int bc = tid >> 2, bk = (tid & 3) * 4;
    const float* Brow = whh + (size_t)((bc>>4)*HE_ + u0 + (bc&15)) * HE_ + bk;
    float acc[2][4] = {{0.f,0.f,0.f,0.f},{0.f,0.f,0.f,0.f}};
    int ry = (tid >> 4) * 2;
    int cx = (tid & 15) * 4;
    for (int kc = 0; kc < HE_; kc += 16) {
        float4 av = make_float4(0.f,0.f,0.f,0.f);
        if (tid < 128)
            av = *(const float4*)(hin + (size_t)(n0 + (tid>>2))*HE_ + kc + (tid&3)*4);
        float4 bv = *(const float4*)(Brow + kc);
        __syncthreads();
        if (tid < 128) {
            int ar = tid>>2, ak = (tid&3)*4;
            As[ak+0][ar]=av.x; As[ak+1][ar]=av.y; As[ak+2][ar]=av.z; As[ak+3][ar]=av.w;
        }
        Bs[bk+0][bc]=bv.x; Bs[bk+1][bc]=bv.y; Bs[bk+2][bc]=bv.z; Bs[bk+3][bc]=bv.w;
        __syncthreads();
        #pragma unroll
        for (int kk = 0; kk < 16; kk++) {
            float a0 = As[kk][ry], a1 = As[kk][ry+1];
            float4 b = *(const float4*)&Bs[kk][cx];
            acc[0][0]+=a0*b.x; acc[0][1]+=a0*b.y; acc[0][2]+=a0*b.z; acc[0][3]+=a0*b.w;
            acc[1][0]+=a1*b.x; acc[1][1]+=a1*b.y; acc[1][2]+=a1*b.z; acc[1][3]+=a1*b.w;
        }
    }
    __shared__ float gs[32][68];
    const float* Gd = g_G[d] + (size_t)t_eff * (N_*G4E_);
    #pragma unroll
    for (int i = 0; i < 2; i++)
        #pragma unroll
        for (int j = 0; j < 4; j++) {
            int col = cx + j;
            int wr = (col>>4)*HE_ + u0 + (col&15);
            gs[ry+i][col] = acc[i][j] + Gd[(size_t)(n0+ry+i)*G4E_ + wr];
        }
    __syncthreads();
    float* hout = g_hst[1-pin][d];
    float* ob = (layer ? g_enc : g_h1) + (size_t)t_eff*(N_*2*HE_);
    for (int p = tid; p < 32*16; p += 256) {
        int row = p>>4, uu = p&15;
        int n = n0+row, ug = u0+uu;
        float gi = gs[row][uu], gf = gs[row][16+uu], gc = gs[row][32+uu], go = gs[row][48+uu];
        float* cp = &g_cst[d][n*HE_ + ug];
        float cv = sigf(gf)*(*cp) + sigf(gi)*tanhf(gc);
        *cp = cv;
        float hv = sigf(go)*tanhf(cv);
        hout[n*HE_ + ug] = hv;
        ob[(size_t)n*(2*HE_) + d*HE_ + ug] = hv;
    }
}

// ---------------- decoder init: dh=0, dc = concat(first_back, first_back) ----------------
__global__ void k_dec_init()
{
    int i = blockIdx.x*blockDim.x + threadIdx.x;
    if (i < N_*HD_) {
        int n = i / HD_, k = i % HD_;
        g_dc[i] = g_enc[(size_t)n*(2*HE_) + HE_ + (k & (HE_-1))];
        g_dh[0][i] = 0.f;
    }
}

// ---------------- decoder LSTM step ----------------
// grid: (HD/16, N/32), 256 threads. A = h_prev + enc[t] computed on load.
__global__ __launch_bounds__(256) void k_lstm_dec(int t, int pin,
        const float* __restrict__ dwhh, const float* __restrict__ dwih,
        const float* __restrict__ db)
{
    int n0 = blockIdx.y * 32;
    int u0 = blockIdx.x * 16;
    const float* hin  = g_dh[pin];
    const float* encT = g_enc + (size_t)t * (N_*HD_);
    __shared__ __align__(16) float As[16][32];
    __shared__ __align__(16) float Bs[16][64];
    int tid = threadIdx.x;
    int bc = tid >> 2, bk = (tid & 3) * 4;
    const float* Brow = dwhh + (size_t)((bc>>4)*HD_ + u0 + (bc&15)) * HD_ + bk;
    float acc[2][4] = {{0.f,0.f,0.f,0.f},{0.f,0.f,0.f,0.f}};
    int ry = (tid >> 4) * 2;
    int cx = (tid & 15) * 4;
    for (int kc = 0; kc < HD_; kc += 16) {
        float4 av = make_float4(0.f,0.f,0.f,0.f);
        if (tid < 128) {
            size_t off = (size_t)(n0 + (tid>>2))*HD_ + kc + (tid&3)*4;
            float4 h4 = *(const float4*)(hin + off);
            float4 e4 = *(const float4*)(encT + off);
            av = make_float4(h4.x+e4.x, h4.y+e4.y, h4.z+e4.z, h4.w+e4.w);
        }
        float4 bv = *(const float4*)(Brow + kc);
        __syncthreads();
        if (tid < 128) {
            int ar = tid>>2, ak = (tid&3)*4;
            As[ak+0][ar]=av.x; As[ak+1][ar]=av.y; As[ak+2][ar]=av.z; As[ak+3][ar]=av.w;
        }
        Bs[bk+0][bc]=bv.x; Bs[bk+1][bc]=bv.y; Bs[bk+2][bc]=bv.z; Bs[bk+3][bc]=bv.w;
        __syncthreads();
        #pragma unroll
        for (int kk = 0; kk < 16; kk++) {
            float a0 = As[kk][ry], a1 = As[kk][ry+1];
            float4 b = *(const float4*)&Bs[kk][cx];
            acc[0][0]+=a0*b.x; acc[0][1]+=a0*b.y; acc[0][2]+=a0*b.z; acc[0][3]+=a0*b.w;
            acc[1][0]+=a1*b.x; acc[1][1]+=a1*b.y; acc[1][2]+=a1*b.z; acc[1][3]+=a1*b.w;
        }
    }
    __shared__ float gs[32][68];
    #pragma unroll
    for (int i = 0; i < 2; i++)
        #pragma unroll
        for (int j = 0; j < 4; j++)
            gs[ry+i][cx+j] = acc[i][j];
    __syncthreads();
    float* hout = g_dh[1-pin];
    for (int p = tid; p < 32*16; p += 256) {
        int row = p>>4, uu = p&15;
        int n = n0+row, ug = u0+uu;
        float wi0=0.f, wi1=0.f, wi2=0.f, wi3=0.f;
        if (t > 0) {
            int idx = g_amax[n];
            wi0 = dwih[(size_t)(ug)*T_ + idx];
            wi1 = dwih[(size_t)(HD_+ug)*T_ + idx];
            wi2 = dwih[(size_t)(2*HD_+ug)*T_ + idx];
            wi3 = dwih[(size_t)(3*HD_+ug)*T_ + idx];
        }
        float gi = gs[row][uu]    + db[ug]        + wi0;
        float gf = gs[row][16+uu] + db[HD_+ug]    + wi1;
        float gc = gs[row][32+uu] + db[2*HD_+ug]  + wi2;
        float go = gs[row][48+uu] + db[3*HD_+ug]  + wi3;
        float* cp = &g_dc[n*HD_ + ug];
        float cv = sigf(gf)*(*cp) + sigf(gi)*tanhf(gc);
        *cp = cv;
        hout[n*HD_ + ug] = sigf(go)*tanhf(cv);
    }
}

// ---------------- decoder output: logits, softmax, prob, loss term, argmax ----------------
// one block per sample n, 128 threads (one per tag j)
__global__ __launch_bounds__(128) void k_dec_out(int t, int ph_new,
        const int* __restrict__ tags, const float* __restrict__ ow,
        const float* __restrict__ ob, float* __restrict__ out)
{
    int n = blockIdx.x, j = threadIdx.x;
    __shared__ __align__(16) float hs[HD_];
    __shared__ float red[T_];
    __shared__ int   redi[T_];
    const float* h = g_dh[ph_new] + (size_t)n*HD_;
    for (int k = j; k < HD_; k += T_) hs[k] = h[k];
    __syncthreads();
    float acc = ob[j];
    const float4* w4 = (const float4*)(ow + (size_t)j*HD_);
    const float4* h4 = (const float4*)hs;
    #pragma unroll 8
    for (int k4 = 0; k4 < HD_/4; k4++) {
        float4 w = w4[k4]; float4 hv = h4[k4];
        acc += w.x*hv.x + w.y*hv.y + w.z*hv.z + w.w*hv.w;
    }
    // max
    red[j] = acc; __syncthreads();
    for (int s = 64; s > 0; s >>= 1) { if (j < s) red[j] = fmaxf(red[j], red[j+s]); __syncthreads(); }
    float mx = red[0]; __syncthreads();
    // sum exp
    float e = expf(acc - mx);
    red[j] = e; __syncthreads();
    for (int s = 64; s > 0; s >>= 1) { if (j < s) red[j] += red[j+s]; __syncthreads(); }
    float sum = red[0];
    float prob = e / sum;
    out[((size_t)n*L_ + t)*T_ + j] = prob;
    int tag = tags[n*L_ + t];
    if (j == tag) g_lterm[t*N_ + n] = -(acc - mx - logf(sum)) / (float)N_;
    __syncthreads();
    // argmax (first index on ties)
    red[j] = acc; redi[j] = j; __syncthreads();
    for (int s = 64; s > 0; s >>= 1) {
        if (j < s) {
            float o = red[j+s]; int oi = redi[j+s];
            if (o > red[j] || (o == red[j] && oi < redi[j])) { red[j] = o; redi[j] = oi; }
        }
        __syncthreads();
    }
    if (j == 0) g_amax[n] = redi[0];
}

// ---------------- deterministic loss reduction ----------------
__global__ void k_loss(float* __restrict__ out)
{
    __shared__ float red[256];
    float s = 0.f;
    for (int i = threadIdx.x; i < L_*N_; i += 256) s += g_lterm[i];
    red[threadIdx.x] = s; __syncthreads();
    for (int st = 128; st > 0; st >>= 1) {
        if (threadIdx.x < st) red[threadIdx.x] += red[threadIdx.x + st];
        __syncthreads();
    }
    if (threadIdx.x == 0) out[(size_t)N_*L_*T_] = red[0];
}

// ---------------- launcher ----------------
extern "C" void kernel_launch(void* const* d_in, const int* in_sizes, int n_in,
                              void* d_out, int out_size)
{
    const int*   ids    = (const int*)  d_in[0];
    const int*   tags   = (const int*)  d_in[1];
    const float* embed  = (const float*)d_in[2];
    const float* e0_wih = (const float*)d_in[3];
    const float* e0_whh = (const float*)d_in[4];
    const float* e0_b   = (const float*)d_in[5];
    const float* e1_wih = (const float*)d_in[6];
    const float* e1_whh = (const float*)d_in[7];
    const float* e1_b   = (const float*)d_in[8];
    const float* dwih   = (const float*)d_in[9];
    const float* dwhh   = (const float*)d_in[10];
    const float* db     = (const float*)d_in[11];
    const float* ow     = (const float*)d_in[12];
    const float* ob     = (const float*)d_in[13];
    float* out = (float*)d_out;

    // 1. embedding
    k_embed<<<(LN_*E_/4 + 255)/256, 256>>>(ids, embed);

    // 2. enc0: precompute input gates, then 160 fused steps
    k_zero_enc<<<(2*2*N_*HE_ + 255)/256, 256>>>();
    {
        dim3 gg(G4E_/128, LN_/128, 2);
        k_gemm_bias<<<gg, 256>>>(0, e0_wih, e0_b, E_);
    }
    {
        dim3 ge(HE_/16, N_/32, 2);
        for (int t = 0; t < L_; t++)
            k_lstm_enc<<<ge, 256>>>(0, t, t & 1, e0_whh);
    }

    // 3. enc1
    k_zero_enc<<<(2*2*N_*HE_ + 255)/256, 256>>>();
    {
        dim3 gg(G4E_/128, LN_/128, 2);
        k_gemm_bias<<<gg, 256>>>(1, e1_wih, e1_b, 2*HE_);
    }
    {
        dim3 ge(HE_/16, N_/32, 2);
        for (int t = 0; t < L_; t++)
            k_lstm_enc<<<ge, 256>>>(1, t, t & 1, e1_whh);
    }

    // 4. decoder
    k_dec_init<<<(N_*HD_ + 255)/256, 256>>>();
    {
        dim3 gd(HD_/16, N_/32);
        for (int t = 0; t < L_; t++) {
            k_lstm_dec<<<gd, 256>>>(t, t & 1, dwhh, dwih, db);
            k_dec_out<<<N_, T_>>>(t, (t + 1) & 1, tags, ow, ob, out);
        }
    }

    // 5. loss
    k_loss<<<1, 256>>>(out);
}